// round 2
// baseline (speedup 1.0000x reference)
#include <cuda_runtime.h>
#include <math.h>

#define NB 4
#define LQ 2048
#define HH 1024
#define NHEAD 16
#define CD 64
#define SCALE 0.03125f   /* 1/sqrt(1024) */

typedef unsigned long long ull;

// ---------------- packed f32x2 helpers (sm_100+ only) ----------------
__device__ __forceinline__ ull f2pack(float lo, float hi) {
    ull r; asm("mov.b64 %0, {%1,%2};" : "=l"(r) : "f"(lo), "f"(hi)); return r;
}
__device__ __forceinline__ void f2unpack(ull v, float &lo, float &hi) {
    asm("mov.b64 {%0,%1}, %2;" : "=f"(lo), "=f"(hi) : "l"(v));
}
__device__ __forceinline__ ull f2fma(ull a, ull b, ull c) {
    ull d; asm("fma.rn.f32x2 %0, %1, %2, %3;" : "=l"(d) : "l"(a), "l"(b), "l"(c)); return d;
}
__device__ __forceinline__ ull f2mul(ull a, ull b) {
    ull d; asm("mul.rn.f32x2 %0, %1, %2;" : "=l"(d) : "l"(a), "l"(b)); return d;
}

// ---------------- scratch (device globals; no allocs allowed) ----------------
__device__ float g_Qp[NB * LQ * HH];
__device__ float g_Kp[NB * LQ * HH];
__device__ float g_Vp[NB * LQ * HH];
__device__ float g_ctx[NB * LQ * HH];

// ---------------- SGEMM: Y = (X @ W + bias) * postscale ----------------
// X: (M,1024) row-major, W: (1024,1024) row-major, M = gridDim.y*128
// BM=BN=128, BK=16, 256 threads, 8x8 per thread, FFMA2 pairs along N.
__device__ __forceinline__ void sgemm_body(const float* __restrict__ X,
                                           const float* __restrict__ W,
                                           const float* __restrict__ bias,
                                           float* __restrict__ Y,
                                           float postscale)
{
    __shared__ float As[16][132];   // [k][m], padded
    __shared__ float Bs[16][128];   // [k][n]

    const int tid = threadIdx.x;
    const int tx = tid & 15, ty = tid >> 4;
    const int bm = blockIdx.y, bn = blockIdx.x;

    const float* Xb = X + (size_t)bm * 128 * HH;
    const float* Wb = W + bn * 128;

    const int ar = tid >> 2;          // 0..63 (A tile row)
    const int ak = (tid & 3) << 2;    // 0,4,8,12 (A tile k base)
    const int br = tid >> 5;          // 0..7   (B tile k row)
    const int bc = (tid & 31) << 2;   // 0..124 (B tile col)

    ull acc[8][4];
    #pragma unroll
    for (int i = 0; i < 8; i++)
        #pragma unroll
        for (int j = 0; j < 4; j++) acc[i][j] = 0ull;

    float4 a0r = *(const float4*)(Xb + (size_t)ar * HH + ak);
    float4 a1r = *(const float4*)(Xb + (size_t)(ar + 64) * HH + ak);
    float4 b0r = *(const float4*)(Wb + (size_t)br * HH + bc);
    float4 b1r = *(const float4*)(Wb + (size_t)(br + 8) * HH + bc);

    for (int kt = 0; kt < HH; kt += 16) {
        __syncthreads();
        As[ak + 0][ar] = a0r.x;  As[ak + 1][ar] = a0r.y;
        As[ak + 2][ar] = a0r.z;  As[ak + 3][ar] = a0r.w;
        As[ak + 0][ar + 64] = a1r.x;  As[ak + 1][ar + 64] = a1r.y;
        As[ak + 2][ar + 64] = a1r.z;  As[ak + 3][ar + 64] = a1r.w;
        *(float4*)&Bs[br][bc]     = b0r;
        *(float4*)&Bs[br + 8][bc] = b1r;
        __syncthreads();

        if (kt + 16 < HH) {  // prefetch next tile into regs (overlaps compute)
            a0r = *(const float4*)(Xb + (size_t)ar * HH + (kt + 16) + ak);
            a1r = *(const float4*)(Xb + (size_t)(ar + 64) * HH + (kt + 16) + ak);
            b0r = *(const float4*)(Wb + (size_t)(kt + 16 + br) * HH + bc);
            b1r = *(const float4*)(Wb + (size_t)(kt + 16 + br + 8) * HH + bc);
        }

        #pragma unroll
        for (int k = 0; k < 16; k++) {
            float4 av0 = *(const float4*)&As[k][ty * 8];
            float4 av1 = *(const float4*)&As[k][ty * 8 + 4];
            ulonglong2 bv0 = *(const ulonglong2*)&Bs[k][tx * 8];
            ulonglong2 bv1 = *(const ulonglong2*)&Bs[k][tx * 8 + 4];
            float aa[8] = {av0.x, av0.y, av0.z, av0.w, av1.x, av1.y, av1.z, av1.w};
            #pragma unroll
            for (int i = 0; i < 8; i++) {
                ull ap = f2pack(aa[i], aa[i]);
                acc[i][0] = f2fma(ap, bv0.x, acc[i][0]);
                acc[i][1] = f2fma(ap, bv0.y, acc[i][1]);
                acc[i][2] = f2fma(ap, bv1.x, acc[i][2]);
                acc[i][3] = f2fma(ap, bv1.y, acc[i][3]);
            }
        }
    }

    const int row0 = bm * 128 + ty * 8;
    const int col0 = bn * 128 + tx * 8;
    float4 bb0 = *(const float4*)(bias + col0);
    float4 bb1 = *(const float4*)(bias + col0 + 4);
    float bbf[8] = {bb0.x, bb0.y, bb0.z, bb0.w, bb1.x, bb1.y, bb1.z, bb1.w};

    #pragma unroll
    for (int i = 0; i < 8; i++) {
        float c[8];
        f2unpack(acc[i][0], c[0], c[1]);
        f2unpack(acc[i][1], c[2], c[3]);
        f2unpack(acc[i][2], c[4], c[5]);
        f2unpack(acc[i][3], c[6], c[7]);
        float4 o0, o1;
        o0.x = (c[0] + bbf[0]) * postscale;  o0.y = (c[1] + bbf[1]) * postscale;
        o0.z = (c[2] + bbf[2]) * postscale;  o0.w = (c[3] + bbf[3]) * postscale;
        o1.x = (c[4] + bbf[4]) * postscale;  o1.y = (c[5] + bbf[5]) * postscale;
        o1.z = (c[6] + bbf[6]) * postscale;  o1.w = (c[7] + bbf[7]) * postscale;
        *(float4*)(Y + (size_t)(row0 + i) * HH + col0)     = o0;
        *(float4*)(Y + (size_t)(row0 + i) * HH + col0 + 4) = o1;
    }
}

__global__ void __launch_bounds__(256)
k_qkv(const float* __restrict__ Q, const float* __restrict__ K, const float* __restrict__ V,
      const float* __restrict__ Wq, const float* __restrict__ Wk, const float* __restrict__ Wv,
      const float* __restrict__ bq, const float* __restrict__ bk, const float* __restrict__ bv)
{
    const int z = blockIdx.z;
    const float* X = (z == 0) ? Q : (z == 1) ? K : V;
    const float* W = (z == 0) ? Wq : (z == 1) ? Wk : Wv;
    const float* b = (z == 0) ? bq : (z == 1) ? bk : bv;
    float*       Yp = (z == 0) ? g_Qp : (z == 1) ? g_Kp : g_Vp;
    const float  sc = (z == 2) ? 1.0f : SCALE;  // scale applied to Q AND K (as in ref)
    sgemm_body(X, W, b, Yp, sc);
}

__global__ void __launch_bounds__(256)
k_out(const float* __restrict__ Wo, const float* __restrict__ bo, float* __restrict__ out)
{
    sgemm_body(g_ctx, Wo, bo, out, 1.0f);
}

// ---------------- causal flash attention ----------------
// The "raw reshape" means head h of batch n is the contiguous slab
//   base = (n*16 + h) * 128 * 1024  viewed as a 2048x64 row-major matrix.
// BR = BC = 64, block = 256 threads (16x16), thread computes 4x4 of S and O.
#define ATTN_SMEM ((68 + 68 + 64 + 68) * 64 * 4 + 64 * 4)

__global__ void __launch_bounds__(256)
k_attn(const int* __restrict__ key_mask)
{
    extern __shared__ float sm[];
    float* Qt  = sm;                 // [64][68] transposed: Qt[k][i]
    float* Kt  = Qt + 64 * 68;       // [64][68] transposed: Kt[k][j]
    float* Vs  = Kt + 64 * 68;       // [64][64] natural:    Vs[j][v]
    float* Pt  = Vs + 64 * 64;       // [64][68] transposed: Pt[j][i]
    int*   kms = (int*)(Pt + 64 * 68);

    const int tid = threadIdx.x;
    const int tx = tid & 15, ty = tid >> 4;
    const int bh = blockIdx.y;               // n*16 + head
    const int n  = bh >> 4;
    const size_t base = (size_t)bh * (128 * HH);
    const float* Qh = g_Qp + base;
    const float* Kh = g_Kp + base;
    const float* Vh = g_Vp + base;
    float*       Ch = g_ctx + base;

    const int qt    = (int)gridDim.x - 1 - (int)blockIdx.x;  // heavy tiles first
    const int qbase = qt * 64;

    const int lr = tid >> 2;           // 0..63  (tile row)
    const int lk = (tid & 3) << 2;     // 0,4,8,12 (k base; +16*c covers 0..63)

    // ---- load Q tile (64x64), transposed: 4 float4 per thread ----
    #pragma unroll
    for (int c = 0; c < 4; c++) {
        const int kk = lk + 16 * c;
        float4 v = *(const float4*)(Qh + (size_t)(qbase + lr) * CD + kk);
        Qt[(kk + 0) * 68 + lr] = v.x;
        Qt[(kk + 1) * 68 + lr] = v.y;
        Qt[(kk + 2) * 68 + lr] = v.z;
        Qt[(kk + 3) * 68 + lr] = v.w;
    }

    float m[4], l[4];
    ull o2[4][2];
    #pragma unroll
    for (int r = 0; r < 4; r++) {
        m[r] = -INFINITY; l[r] = 0.0f; o2[r][0] = 0ull; o2[r][1] = 0ull;
    }

    const int i0 = 4 * ty;   // local row base  (query)
    const int j0 = 4 * tx;   // local col base  (key)

    for (int jt = 0; jt <= qt; jt++) {
        __syncthreads();
        // ---- load K (transposed) and V (natural), full 64x64 each ----
        #pragma unroll
        for (int c = 0; c < 4; c++) {
            const int kk = lk + 16 * c;
            float4 kv = *(const float4*)(Kh + (size_t)(jt * 64 + lr) * CD + kk);
            Kt[(kk + 0) * 68 + lr] = kv.x;
            Kt[(kk + 1) * 68 + lr] = kv.y;
            Kt[(kk + 2) * 68 + lr] = kv.z;
            Kt[(kk + 3) * 68 + lr] = kv.w;
            float4 vv = *(const float4*)(Vh + (size_t)(jt * 64 + lr) * CD + kk);
            *(float4*)&Vs[lr * CD + kk] = vv;
        }
        if (tid < 64) kms[tid] = key_mask[n * LQ + jt * 64 + tid];
        __syncthreads();

        // ---- S = Q K^T (pairs along key-cols) ----
        ull s2[4][2];
        #pragma unroll
        for (int r = 0; r < 4; r++) { s2[r][0] = 0ull; s2[r][1] = 0ull; }

        #pragma unroll 8
        for (int k = 0; k < 64; k++) {
            float4 aq = *(const float4*)&Qt[k * 68 + i0];
            ulonglong2 bk2 = *(const ulonglong2*)&Kt[k * 68 + j0];
            ull a;
            a = f2pack(aq.x, aq.x); s2[0][0] = f2fma(a, bk2.x, s2[0][0]); s2[0][1] = f2fma(a, bk2.y, s2[0][1]);
            a = f2pack(aq.y, aq.y); s2[1][0] = f2fma(a, bk2.x, s2[1][0]); s2[1][1] = f2fma(a, bk2.y, s2[1][1]);
            a = f2pack(aq.z, aq.z); s2[2][0] = f2fma(a, bk2.x, s2[2][0]); s2[2][1] = f2fma(a, bk2.y, s2[2][1]);
            a = f2pack(aq.w, aq.w); s2[3][0] = f2fma(a, bk2.x, s2[3][0]); s2[3][1] = f2fma(a, bk2.y, s2[3][1]);
        }

        float S[4][4];
        #pragma unroll
        for (int r = 0; r < 4; r++) {
            f2unpack(s2[r][0], S[r][0], S[r][1]);
            f2unpack(s2[r][1], S[r][2], S[r][3]);
        }

        // ---- mask (key_mask + causal on diagonal tile) ----
        const bool diag = (jt == qt);
        #pragma unroll
        for (int c = 0; c < 4; c++) {
            const bool kmok = (kms[j0 + c] != 0);
            #pragma unroll
            for (int r = 0; r < 4; r++) {
                const bool ok = kmok && (!diag || (j0 + c) <= (i0 + r));
                if (!ok) S[r][c] = -INFINITY;
            }
        }

        // ---- online softmax (row stats shared by the 16 tx-threads via shfl) ----
        #pragma unroll
        for (int r = 0; r < 4; r++) {
            float mx = fmaxf(fmaxf(S[r][0], S[r][1]), fmaxf(S[r][2], S[r][3]));
            #pragma unroll
            for (int d = 8; d > 0; d >>= 1) mx = fmaxf(mx, __shfl_xor_sync(0xffffffffu, mx, d));
            const float mn = fmaxf(m[r], mx);

            float p0, p1, p2, p3, alpha;
            if (mn == -INFINITY) {   // fully masked row so far
                alpha = 1.0f; p0 = p1 = p2 = p3 = 0.0f;
            } else {
                alpha = __expf(m[r] - mn);
                p0 = __expf(S[r][0] - mn);
                p1 = __expf(S[r][1] - mn);
                p2 = __expf(S[r][2] - mn);
                p3 = __expf(S[r][3] - mn);
            }
            m[r] = mn;

            float rs = p0 + p1 + p2 + p3;
            #pragma unroll
            for (int d = 8; d > 0; d >>= 1) rs += __shfl_xor_sync(0xffffffffu, rs, d);
            l[r] = l[r] * alpha + rs;

            ull ap = f2pack(alpha, alpha);
            o2[r][0] = f2mul(o2[r][0], ap);
            o2[r][1] = f2mul(o2[r][1], ap);

            Pt[(j0 + 0) * 68 + i0 + r] = p0;
            Pt[(j0 + 1) * 68 + i0 + r] = p1;
            Pt[(j0 + 2) * 68 + i0 + r] = p2;
            Pt[(j0 + 3) * 68 + i0 + r] = p3;
        }
        __syncthreads();

        // ---- O += P @ V (pairs along value-cols) ----
        #pragma unroll 8
        for (int j = 0; j < 64; j++) {
            float4 pv = *(const float4*)&Pt[j * 68 + i0];
            ulonglong2 vv = *(const ulonglong2*)&Vs[j * CD + j0];
            ull a;
            a = f2pack(pv.x, pv.x); o2[0][0] = f2fma(a, vv.x, o2[0][0]); o2[0][1] = f2fma(a, vv.y, o2[0][1]);
            a = f2pack(pv.y, pv.y); o2[1][0] = f2fma(a, vv.x, o2[1][0]); o2[1][1] = f2fma(a, vv.y, o2[1][1]);
            a = f2pack(pv.z, pv.z); o2[2][0] = f2fma(a, vv.x, o2[2][0]); o2[2][1] = f2fma(a, vv.y, o2[2][1]);
            a = f2pack(pv.w, pv.w); o2[3][0] = f2fma(a, vv.x, o2[3][0]); o2[3][1] = f2fma(a, vv.y, o2[3][1]);
        }
    }

    // ---- normalize + write context (contiguous slab = raw-reshape concats) ----
    #pragma unroll
    for (int r = 0; r < 4; r++) {
        const float inv = 1.0f / l[r];
        float o0, o1, o2f, o3;
        f2unpack(o2[r][0], o0, o1);
        f2unpack(o2[r][1], o2f, o3);
        float4 ov;
        ov.x = o0 * inv; ov.y = o1 * inv; ov.z = o2f * inv; ov.w = o3 * inv;
        *(float4*)(Ch + (size_t)(qbase + i0 + r) * CD + j0) = ov;
    }
}

// ---------------- launch ----------------
extern "C" void kernel_launch(void* const* d_in, const int* in_sizes, int n_in,
                              void* d_out, int out_size)
{
    const float* Q  = (const float*)d_in[0];
    const float* K  = (const float*)d_in[1];
    const float* V  = (const float*)d_in[2];
    const int*   km = (const int*)  d_in[3];
    const float* Wq = (const float*)d_in[4];
    const float* bq = (const float*)d_in[5];
    const float* Wk = (const float*)d_in[6];
    const float* bk = (const float*)d_in[7];
    const float* Wv = (const float*)d_in[8];
    const float* bv = (const float*)d_in[9];
    const float* Wo = (const float*)d_in[10];
    const float* bo = (const float*)d_in[11];
    float* out = (float*)d_out;

    dim3 gqkv(HH / 128, (NB * LQ) / 128, 3);
    k_qkv<<<gqkv, 256>>>(Q, K, V, Wq, Wk, Wv, bq, bk, bv);

    cudaFuncSetAttribute(k_attn, cudaFuncAttributeMaxDynamicSharedMemorySize, ATTN_SMEM);
    k_attn<<<dim3(LQ / 64, NB * NHEAD), 256, ATTN_SMEM>>>(km);

    dim3 gout(HH / 128, (NB * LQ) / 128, 1);
    k_out<<<gout, 256>>>(Wo, bo, out);
}

// round 4
// speedup vs baseline: 1.2703x; 1.2703x over previous
#include <cuda_runtime.h>
#include <cuda_bf16.h>
#include <math.h>
#include <cstdint>

#define NB 4
#define LQ 2048
#define HH 1024
#define NHEAD 16
#define CD 64
#define SCALE 0.03125f   /* 1/sqrt(1024) */
#define ELEMS ((size_t)NB * LQ * HH)   /* 8388608 */

typedef unsigned long long ull;

// ================= packed f32x2 helpers (attention kernel) =================
__device__ __forceinline__ ull f2pack(float lo, float hi) {
    ull r; asm("mov.b64 %0, {%1,%2};" : "=l"(r) : "f"(lo), "f"(hi)); return r;
}
__device__ __forceinline__ void f2unpack(ull v, float &lo, float &hi) {
    asm("mov.b64 {%0,%1}, %2;" : "=f"(lo), "=f"(hi) : "l"(v));
}
__device__ __forceinline__ ull f2fma(ull a, ull b, ull c) {
    ull d; asm("fma.rn.f32x2 %0, %1, %2, %3;" : "=l"(d) : "l"(a), "l"(b), "l"(c)); return d;
}
__device__ __forceinline__ ull f2mul(ull a, ull b) {
    ull d; asm("mul.rn.f32x2 %0, %1, %2;" : "=l"(d) : "l"(a), "l"(b)); return d;
}

// ================= cp.async helpers (sm_80+, plain target OK) =================
__device__ __forceinline__ uint32_t smem_u32(const void* p) {
    uint32_t a;
    asm("{ .reg .u64 t; cvta.to.shared.u64 t, %1; cvt.u32.u64 %0, t; }" : "=r"(a) : "l"(p));
    return a;
}
#define CP_ASYNC16(sa, gp) \
    asm volatile("cp.async.cg.shared.global [%0], [%1], 16;" :: "r"(sa), "l"(gp) : "memory")
#define CP_COMMIT() asm volatile("cp.async.commit_group;" ::: "memory")
#define CP_WAIT0()  asm volatile("cp.async.wait_group 0;" ::: "memory")

// bf16 warp MMA: D(16x8) += A(16x16) * B(16x8);  A row-major, B col-major
__device__ __forceinline__ void mma_bf16(float* d, const uint32_t* a, const uint32_t* b) {
    asm volatile(
        "mma.sync.aligned.m16n8k16.row.col.f32.bf16.bf16.f32 "
        "{%0,%1,%2,%3}, {%4,%5,%6,%7}, {%8,%9}, {%0,%1,%2,%3};"
        : "+f"(d[0]), "+f"(d[1]), "+f"(d[2]), "+f"(d[3])
        : "r"(a[0]), "r"(a[1]), "r"(a[2]), "r"(a[3]), "r"(b[0]), "r"(b[1]));
}

// ================= scratch (device globals) =================
__device__ float g_Qp[ELEMS];
__device__ float g_Kp[ELEMS];
__device__ float g_Vp[ELEMS];
__device__ float g_ctx[ELEMS];
__device__ __nv_bfloat16 g_xh[3 * ELEMS];      // bf16-hi of Q,K,V inputs
__device__ __nv_bfloat16 g_xl[3 * ELEMS];      // bf16-lo
__device__ __nv_bfloat16 g_ch[ELEMS];          // bf16-hi of ctx
__device__ __nv_bfloat16 g_cl[ELEMS];
__device__ __nv_bfloat16 g_wt_h[4 * HH * HH];  // W^T hi (Wq,Wk,Wv,Wo)  [N][K]
__device__ __nv_bfloat16 g_wt_l[4 * HH * HH];  // W^T lo

// ================= prep kernels =================
__global__ void __launch_bounds__(256)
k_prep_x(const float* __restrict__ src, int sel)
{
    const float* s = (sel == 3) ? g_ctx : src;
    __nv_bfloat16* dh = (sel == 3) ? g_ch : g_xh + (size_t)sel * ELEMS;
    __nv_bfloat16* dl = (sel == 3) ? g_cl : g_xl + (size_t)sel * ELEMS;
    size_t i = ((size_t)blockIdx.x * 256 + threadIdx.x) * 4;
    float4 v = *(const float4*)(s + i);
    __nv_bfloat16 h0 = __float2bfloat16(v.x);
    __nv_bfloat16 h1 = __float2bfloat16(v.y);
    __nv_bfloat16 h2 = __float2bfloat16(v.z);
    __nv_bfloat16 h3 = __float2bfloat16(v.w);
    __nv_bfloat16 l0 = __float2bfloat16(v.x - __bfloat162float(h0));
    __nv_bfloat16 l1 = __float2bfloat16(v.y - __bfloat162float(h1));
    __nv_bfloat16 l2 = __float2bfloat16(v.z - __bfloat162float(h2));
    __nv_bfloat16 l3 = __float2bfloat16(v.w - __bfloat162float(h3));
    __nv_bfloat162* dh2 = (__nv_bfloat162*)(dh + i);
    __nv_bfloat162* dl2 = (__nv_bfloat162*)(dl + i);
    dh2[0] = __halves2bfloat162(h0, h1);
    dh2[1] = __halves2bfloat162(h2, h3);
    dl2[0] = __halves2bfloat162(l0, l1);
    dl2[1] = __halves2bfloat162(l2, l3);
}

__global__ void __launch_bounds__(256)
k_prep_w(const float* __restrict__ Wq, const float* __restrict__ Wk,
         const float* __restrict__ Wv, const float* __restrict__ Wo)
{
    const int z = blockIdx.z;
    const float* W = (z == 0) ? Wq : (z == 1) ? Wk : (z == 2) ? Wv : Wo;
    __shared__ float t[32][33];
    const int n0 = blockIdx.x * 32, k0 = blockIdx.y * 32;
    const int tx = threadIdx.x, ty = threadIdx.y;
    for (int r = ty; r < 32; r += 8) t[r][tx] = W[(size_t)(k0 + r) * HH + n0 + tx];
    __syncthreads();
    __nv_bfloat16* dh = g_wt_h + (size_t)z * HH * HH;
    __nv_bfloat16* dl = g_wt_l + (size_t)z * HH * HH;
    for (int rr = ty; rr < 32; rr += 8) {
        float v = t[tx][rr];     // = W[k0+tx][n0+rr]
        __nv_bfloat16 h = __float2bfloat16(v);
        dh[(size_t)(n0 + rr) * HH + k0 + tx] = h;
        dl[(size_t)(n0 + rr) * HH + k0 + tx] = __float2bfloat16(v - __bfloat162float(h));
    }
}

// ================= mma.sync GEMM =================
// Y[8192,1024] = split-bf16( X @ W ) + bias, * postscale.
// CTA tile 128x128, 8 warps (4M x 2N), warp tile 32x64.
// K_eff = 3*1024 (Xh*Wh, Xh*Wl, Xl*Wh), BK=32, cp.async double buffer.
#define APAD 40          /* padded k-stride in bf16 (80B = 20 banks, conflict-free) */
#define NCHUNK 96

__global__ void __launch_bounds__(256)
k_gemm(int sel, const float* __restrict__ bias, float* __restrict__ Yext, float postscale)
{
    __shared__ __align__(16) __nv_bfloat16 sA[2][128 * APAD];
    __shared__ __align__(16) __nv_bfloat16 sB[2][128 * APAD];

    const int tid  = threadIdx.x;
    const int wid  = tid >> 5, lane = tid & 31;
    const int g    = lane >> 2, tig = lane & 3;
    const int wm   = (wid & 3) * 32;
    const int wn   = (wid >> 2) * 64;

    const __nv_bfloat16* Ah = (sel == 3) ? g_ch : g_xh + (size_t)sel * ELEMS;
    const __nv_bfloat16* Al = (sel == 3) ? g_cl : g_xl + (size_t)sel * ELEMS;
    const __nv_bfloat16* Bh = g_wt_h + (size_t)sel * HH * HH;
    const __nv_bfloat16* Bl = g_wt_l + (size_t)sel * HH * HH;
    float* Y = (sel == 0) ? g_Qp : (sel == 1) ? g_Kp : (sel == 2) ? g_Vp : Yext;

    const int nbase = blockIdx.x * 128;
    const int mbase = blockIdx.y * 128;

    // load mapping: 512 uint4 per tile (A and B each); thread does 2 of each
    const int u0 = tid, u1 = tid + 256;
    const int ar0 = u0 >> 2, aq0 = u0 & 3;
    const int ar1 = u1 >> 2, aq1 = u1 & 3;

    const uint32_t sA0 = smem_u32(&sA[0][0]);
    const uint32_t sB0 = smem_u32(&sB[0][0]);
    const uint32_t bufBytes = 128 * APAD * 2;

    #define LOAD_CHUNK(c, s) do {                                                   \
        const int _seg = (c) >> 5;                                                  \
        const int _kt  = ((c) & 31) << 5;                                           \
        const __nv_bfloat16* _a = (_seg == 2) ? Al : Ah;                            \
        const __nv_bfloat16* _b = (_seg == 1) ? Bl : Bh;                            \
        CP_ASYNC16(sA0 + (s) * bufBytes + (ar0 * APAD + aq0 * 8) * 2,               \
                   _a + (size_t)(mbase + ar0) * HH + _kt + aq0 * 8);                \
        CP_ASYNC16(sA0 + (s) * bufBytes + (ar1 * APAD + aq1 * 8) * 2,               \
                   _a + (size_t)(mbase + ar1) * HH + _kt + aq1 * 8);                \
        CP_ASYNC16(sB0 + (s) * bufBytes + (ar0 * APAD + aq0 * 8) * 2,               \
                   _b + (size_t)(nbase + ar0) * HH + _kt + aq0 * 8);                \
        CP_ASYNC16(sB0 + (s) * bufBytes + (ar1 * APAD + aq1 * 8) * 2,               \
                   _b + (size_t)(nbase + ar1) * HH + _kt + aq1 * 8);                \
        CP_COMMIT();                                                                \
    } while (0)

    float acc[2][8][4];
    #pragma unroll
    for (int mt = 0; mt < 2; mt++)
        #pragma unroll
        for (int nt = 0; nt < 8; nt++)
            #pragma unroll
            for (int q = 0; q < 4; q++) acc[mt][nt][q] = 0.0f;

    LOAD_CHUNK(0, 0);

    for (int c = 0; c < NCHUNK; c++) {
        const int s = c & 1;
        CP_WAIT0();
        __syncthreads();
        if (c + 1 < NCHUNK) LOAD_CHUNK(c + 1, s ^ 1);

        const __nv_bfloat16* a_s = sA[s];
        const __nv_bfloat16* b_s = sB[s];
        #pragma unroll
        for (int ks = 0; ks < 32; ks += 16) {
            uint32_t af[2][4], bf[8][2];
            #pragma unroll
            for (int mt = 0; mt < 2; mt++) {
                const int r0 = (wm + mt * 16 + g) * APAD + ks + tig * 2;
                const int r1 = (wm + mt * 16 + g + 8) * APAD + ks + tig * 2;
                af[mt][0] = *(const uint32_t*)(a_s + r0);
                af[mt][1] = *(const uint32_t*)(a_s + r1);
                af[mt][2] = *(const uint32_t*)(a_s + r0 + 8);
                af[mt][3] = *(const uint32_t*)(a_s + r1 + 8);
            }
            #pragma unroll
            for (int nt = 0; nt < 8; nt++) {
                const int rb = (wn + nt * 8 + g) * APAD + ks + tig * 2;
                bf[nt][0] = *(const uint32_t*)(b_s + rb);
                bf[nt][1] = *(const uint32_t*)(b_s + rb + 8);
            }
            #pragma unroll
            for (int mt = 0; mt < 2; mt++)
                #pragma unroll
                for (int nt = 0; nt < 8; nt++)
                    mma_bf16(acc[mt][nt], af[mt], bf[nt]);
        }
        __syncthreads();
    }

    // epilogue
    #pragma unroll
    for (int mt = 0; mt < 2; mt++) {
        const int r0 = mbase + wm + mt * 16 + g;
        #pragma unroll
        for (int nt = 0; nt < 8; nt++) {
            const int n = nbase + wn + nt * 8 + tig * 2;
            const float2 bb = *(const float2*)(bias + n);
            float2 o0, o1;
            o0.x = (acc[mt][nt][0] + bb.x) * postscale;
            o0.y = (acc[mt][nt][1] + bb.y) * postscale;
            o1.x = (acc[mt][nt][2] + bb.x) * postscale;
            o1.y = (acc[mt][nt][3] + bb.y) * postscale;
            *(float2*)(Y + (size_t)r0 * HH + n)       = o0;
            *(float2*)(Y + (size_t)(r0 + 8) * HH + n) = o1;
        }
    }
}

// ================= causal flash attention (fp32, unchanged) =================
#define ATTN_SMEM ((68 + 68 + 64 + 68) * 64 * 4 + 64 * 4)

__global__ void __launch_bounds__(256)
k_attn(const int* __restrict__ key_mask)
{
    extern __shared__ float smf[];
    float* Qt  = smf;
    float* Kt  = Qt + 64 * 68;
    float* Vs  = Kt + 64 * 68;
    float* Pt  = Vs + 64 * 64;
    int*   kms = (int*)(Pt + 64 * 68);

    const int tid = threadIdx.x;
    const int tx = tid & 15, ty = tid >> 4;
    const int bh = blockIdx.y;
    const int n  = bh >> 4;
    const size_t base = (size_t)bh * (128 * HH);
    const float* Qh = g_Qp + base;
    const float* Kh = g_Kp + base;
    const float* Vh = g_Vp + base;
    float*       Ch = g_ctx + base;

    const int qt    = (int)gridDim.x - 1 - (int)blockIdx.x;
    const int qbase = qt * 64;

    const int lr = tid >> 2;
    const int lk = (tid & 3) << 2;

    #pragma unroll
    for (int c = 0; c < 4; c++) {
        const int kk = lk + 16 * c;
        float4 v = *(const float4*)(Qh + (size_t)(qbase + lr) * CD + kk);
        Qt[(kk + 0) * 68 + lr] = v.x;
        Qt[(kk + 1) * 68 + lr] = v.y;
        Qt[(kk + 2) * 68 + lr] = v.z;
        Qt[(kk + 3) * 68 + lr] = v.w;
    }

    float m[4], l[4];
    ull o2[4][2];
    #pragma unroll
    for (int r = 0; r < 4; r++) { m[r] = -INFINITY; l[r] = 0.0f; o2[r][0] = 0ull; o2[r][1] = 0ull; }

    const int i0 = 4 * ty;
    const int j0 = 4 * tx;

    for (int jt = 0; jt <= qt; jt++) {
        __syncthreads();
        #pragma unroll
        for (int c = 0; c < 4; c++) {
            const int kk = lk + 16 * c;
            float4 kv = *(const float4*)(Kh + (size_t)(jt * 64 + lr) * CD + kk);
            Kt[(kk + 0) * 68 + lr] = kv.x;
            Kt[(kk + 1) * 68 + lr] = kv.y;
            Kt[(kk + 2) * 68 + lr] = kv.z;
            Kt[(kk + 3) * 68 + lr] = kv.w;
            float4 vv = *(const float4*)(Vh + (size_t)(jt * 64 + lr) * CD + kk);
            *(float4*)&Vs[lr * CD + kk] = vv;
        }
        if (tid < 64) kms[tid] = key_mask[n * LQ + jt * 64 + tid];
        __syncthreads();

        ull s2[4][2];
        #pragma unroll
        for (int r = 0; r < 4; r++) { s2[r][0] = 0ull; s2[r][1] = 0ull; }

        #pragma unroll 8
        for (int k = 0; k < 64; k++) {
            float4 aq = *(const float4*)&Qt[k * 68 + i0];
            ulonglong2 bk2 = *(const ulonglong2*)&Kt[k * 68 + j0];
            ull a;
            a = f2pack(aq.x, aq.x); s2[0][0] = f2fma(a, bk2.x, s2[0][0]); s2[0][1] = f2fma(a, bk2.y, s2[0][1]);
            a = f2pack(aq.y, aq.y); s2[1][0] = f2fma(a, bk2.x, s2[1][0]); s2[1][1] = f2fma(a, bk2.y, s2[1][1]);
            a = f2pack(aq.z, aq.z); s2[2][0] = f2fma(a, bk2.x, s2[2][0]); s2[2][1] = f2fma(a, bk2.y, s2[2][1]);
            a = f2pack(aq.w, aq.w); s2[3][0] = f2fma(a, bk2.x, s2[3][0]); s2[3][1] = f2fma(a, bk2.y, s2[3][1]);
        }

        float S[4][4];
        #pragma unroll
        for (int r = 0; r < 4; r++) {
            f2unpack(s2[r][0], S[r][0], S[r][1]);
            f2unpack(s2[r][1], S[r][2], S[r][3]);
        }

        const bool diag = (jt == qt);
        #pragma unroll
        for (int c = 0; c < 4; c++) {
            const bool kmok = (kms[j0 + c] != 0);
            #pragma unroll
            for (int r = 0; r < 4; r++) {
                const bool ok = kmok && (!diag || (j0 + c) <= (i0 + r));
                if (!ok) S[r][c] = -INFINITY;
            }
        }

        #pragma unroll
        for (int r = 0; r < 4; r++) {
            float mx = fmaxf(fmaxf(S[r][0], S[r][1]), fmaxf(S[r][2], S[r][3]));
            #pragma unroll
            for (int d = 8; d > 0; d >>= 1) mx = fmaxf(mx, __shfl_xor_sync(0xffffffffu, mx, d));
            const float mn = fmaxf(m[r], mx);

            float p0, p1, p2, p3, alpha;
            if (mn == -INFINITY) {
                alpha = 1.0f; p0 = p1 = p2 = p3 = 0.0f;
            } else {
                alpha = __expf(m[r] - mn);
                p0 = __expf(S[r][0] - mn);
                p1 = __expf(S[r][1] - mn);
                p2 = __expf(S[r][2] - mn);
                p3 = __expf(S[r][3] - mn);
            }
            m[r] = mn;

            float rs = p0 + p1 + p2 + p3;
            #pragma unroll
            for (int d = 8; d > 0; d >>= 1) rs += __shfl_xor_sync(0xffffffffu, rs, d);
            l[r] = l[r] * alpha + rs;

            ull ap = f2pack(alpha, alpha);
            o2[r][0] = f2mul(o2[r][0], ap);
            o2[r][1] = f2mul(o2[r][1], ap);

            Pt[(j0 + 0) * 68 + i0 + r] = p0;
            Pt[(j0 + 1) * 68 + i0 + r] = p1;
            Pt[(j0 + 2) * 68 + i0 + r] = p2;
            Pt[(j0 + 3) * 68 + i0 + r] = p3;
        }
        __syncthreads();

        #pragma unroll 8
        for (int j = 0; j < 64; j++) {
            float4 pv = *(const float4*)&Pt[j * 68 + i0];
            ulonglong2 vv = *(const ulonglong2*)&Vs[j * CD + j0];
            ull a;
            a = f2pack(pv.x, pv.x); o2[0][0] = f2fma(a, vv.x, o2[0][0]); o2[0][1] = f2fma(a, vv.y, o2[0][1]);
            a = f2pack(pv.y, pv.y); o2[1][0] = f2fma(a, vv.x, o2[1][0]); o2[1][1] = f2fma(a, vv.y, o2[1][1]);
            a = f2pack(pv.z, pv.z); o2[2][0] = f2fma(a, vv.x, o2[2][0]); o2[2][1] = f2fma(a, vv.y, o2[2][1]);
            a = f2pack(pv.w, pv.w); o2[3][0] = f2fma(a, vv.x, o2[3][0]); o2[3][1] = f2fma(a, vv.y, o2[3][1]);
        }
    }

    #pragma unroll
    for (int r = 0; r < 4; r++) {
        const float inv = 1.0f / l[r];
        float o0, o1, o2f, o3;
        f2unpack(o2[r][0], o0, o1);
        f2unpack(o2[r][1], o2f, o3);
        float4 ov;
        ov.x = o0 * inv; ov.y = o1 * inv; ov.z = o2f * inv; ov.w = o3 * inv;
        *(float4*)(Ch + (size_t)(qbase + i0 + r) * CD + j0) = ov;
    }
}

// ================= launch =================
extern "C" void kernel_launch(void* const* d_in, const int* in_sizes, int n_in,
                              void* d_out, int out_size)
{
    const float* Q  = (const float*)d_in[0];
    const float* K  = (const float*)d_in[1];
    const float* V  = (const float*)d_in[2];
    const int*   km = (const int*)  d_in[3];
    const float* Wq = (const float*)d_in[4];
    const float* bq = (const float*)d_in[5];
    const float* Wk = (const float*)d_in[6];
    const float* bk = (const float*)d_in[7];
    const float* Wv = (const float*)d_in[8];
    const float* bv = (const float*)d_in[9];
    const float* Wo = (const float*)d_in[10];
    const float* bo = (const float*)d_in[11];
    float* out = (float*)d_out;

    cudaFuncSetAttribute(k_attn, cudaFuncAttributeMaxDynamicSharedMemorySize, ATTN_SMEM);

    // prep: W transpose+split, X splits
    k_prep_w<<<dim3(32, 32, 4), dim3(32, 8)>>>(Wq, Wk, Wv, Wo);
    k_prep_x<<<(unsigned)(ELEMS / (4 * 256)), 256>>>(Q, 0);
    k_prep_x<<<(unsigned)(ELEMS / (4 * 256)), 256>>>(K, 1);
    k_prep_x<<<(unsigned)(ELEMS / (4 * 256)), 256>>>(V, 2);

    // QKV projections (HMMA)
    dim3 gg(HH / 128, (NB * LQ) / 128);
    k_gemm<<<gg, 256>>>(0, bq, nullptr, SCALE);
    k_gemm<<<gg, 256>>>(1, bk, nullptr, SCALE);
    k_gemm<<<gg, 256>>>(2, bv, nullptr, 1.0f);

    // attention (fp32)
    k_attn<<<dim3(LQ / 64, NB * NHEAD), 256, ATTN_SMEM>>>(km);

    // out projection
    k_prep_x<<<(unsigned)(ELEMS / (4 * 256)), 256>>>(nullptr, 3);
    k_gemm<<<gg, 256>>>(3, bo, out, 1.0f);
}

// round 5
// speedup vs baseline: 2.2820x; 1.7965x over previous
#include <cuda_runtime.h>
#include <cuda_bf16.h>
#include <math.h>
#include <cstdint>

#define NB 4
#define LQ 2048
#define HH 1024
#define NHEAD 16
#define CD 64
#define SCALE 0.03125f   /* 1/sqrt(1024) */
#define ELEMS ((size_t)NB * LQ * HH)   /* 8388608 */

// ================= async / mma helpers (plain sm_10x target OK) =================
__device__ __forceinline__ uint32_t smem_u32(const void* p) {
    uint32_t a;
    asm("{ .reg .u64 t; cvta.to.shared.u64 t, %1; cvt.u32.u64 %0, t; }" : "=r"(a) : "l"(p));
    return a;
}
#define CP_ASYNC16(sa, gp) \
    asm volatile("cp.async.cg.shared.global [%0], [%1], 16;" :: "r"(sa), "l"(gp) : "memory")
#define CP_COMMIT() asm volatile("cp.async.commit_group;" ::: "memory")
#define CP_WAIT0()  asm volatile("cp.async.wait_group 0;" ::: "memory")

#define LDSM_X4(r0, r1, r2, r3, addr) \
    asm volatile("ldmatrix.sync.aligned.m8n8.x4.shared.b16 {%0,%1,%2,%3}, [%4];" \
        : "=r"(r0), "=r"(r1), "=r"(r2), "=r"(r3) : "r"(addr))
#define LDSM_X4_T(r0, r1, r2, r3, addr) \
    asm volatile("ldmatrix.sync.aligned.m8n8.x4.trans.shared.b16 {%0,%1,%2,%3}, [%4];" \
        : "=r"(r0), "=r"(r1), "=r"(r2), "=r"(r3) : "r"(addr))

// D(16x8,f32) += A(16x16 row) * B(16x8 col), bf16 inputs
__device__ __forceinline__ void mma_bf16(float* d, const uint32_t* a, const uint32_t* b) {
    asm volatile(
        "mma.sync.aligned.m16n8k16.row.col.f32.bf16.bf16.f32 "
        "{%0,%1,%2,%3}, {%4,%5,%6,%7}, {%8,%9}, {%0,%1,%2,%3};"
        : "+f"(d[0]), "+f"(d[1]), "+f"(d[2]), "+f"(d[3])
        : "r"(a[0]), "r"(a[1]), "r"(a[2]), "r"(a[3]), "r"(b[0]), "r"(b[1]));
}

// ================= scratch (device globals) =================
__device__ __nv_bfloat16 g_xh[3 * ELEMS];      // bf16-hi of Q,K,V inputs
__device__ __nv_bfloat16 g_xl[3 * ELEMS];      // bf16-lo
__device__ __nv_bfloat16 g_wt_h[4 * HH * HH];  // W^T hi (Wq,Wk,Wv,Wo)  [N][K]
__device__ __nv_bfloat16 g_wt_l[4 * HH * HH];  // W^T lo
__device__ __nv_bfloat16 g_Qh[ELEMS];          // projected Q (bf16, scaled)
__device__ __nv_bfloat16 g_Kh[ELEMS];          // projected K (bf16, scaled)
__device__ __nv_bfloat16 g_Vh[ELEMS];          // projected V hi
__device__ __nv_bfloat16 g_Vl[ELEMS];          // projected V lo
__device__ __nv_bfloat16 g_ch[ELEMS];          // ctx hi
__device__ __nv_bfloat16 g_cl[ELEMS];          // ctx lo

// ================= prep kernels =================
__global__ void __launch_bounds__(256)
k_prep_x(const float* __restrict__ src, int sel)
{
    __nv_bfloat16* dh = g_xh + (size_t)sel * ELEMS;
    __nv_bfloat16* dl = g_xl + (size_t)sel * ELEMS;
    size_t i = ((size_t)blockIdx.x * 256 + threadIdx.x) * 4;
    float4 v = *(const float4*)(src + i);
    __nv_bfloat16 h0 = __float2bfloat16(v.x);
    __nv_bfloat16 h1 = __float2bfloat16(v.y);
    __nv_bfloat16 h2 = __float2bfloat16(v.z);
    __nv_bfloat16 h3 = __float2bfloat16(v.w);
    __nv_bfloat16 l0 = __float2bfloat16(v.x - __bfloat162float(h0));
    __nv_bfloat16 l1 = __float2bfloat16(v.y - __bfloat162float(h1));
    __nv_bfloat16 l2 = __float2bfloat16(v.z - __bfloat162float(h2));
    __nv_bfloat16 l3 = __float2bfloat16(v.w - __bfloat162float(h3));
    __nv_bfloat162* dh2 = (__nv_bfloat162*)(dh + i);
    __nv_bfloat162* dl2 = (__nv_bfloat162*)(dl + i);
    dh2[0] = __halves2bfloat162(h0, h1);
    dh2[1] = __halves2bfloat162(h2, h3);
    dl2[0] = __halves2bfloat162(l0, l1);
    dl2[1] = __halves2bfloat162(l2, l3);
}

__global__ void __launch_bounds__(256)
k_prep_w(const float* __restrict__ Wq, const float* __restrict__ Wk,
         const float* __restrict__ Wv, const float* __restrict__ Wo)
{
    const int z = blockIdx.z;
    const float* W = (z == 0) ? Wq : (z == 1) ? Wk : (z == 2) ? Wv : Wo;
    __shared__ float t[32][33];
    const int n0 = blockIdx.x * 32, k0 = blockIdx.y * 32;
    const int tx = threadIdx.x, ty = threadIdx.y;
    for (int r = ty; r < 32; r += 8) t[r][tx] = W[(size_t)(k0 + r) * HH + n0 + tx];
    __syncthreads();
    __nv_bfloat16* dh = g_wt_h + (size_t)z * HH * HH;
    __nv_bfloat16* dl = g_wt_l + (size_t)z * HH * HH;
    for (int rr = ty; rr < 32; rr += 8) {
        float v = t[tx][rr];     // = W[k0+tx][n0+rr]
        __nv_bfloat16 h = __float2bfloat16(v);
        dh[(size_t)(n0 + rr) * HH + k0 + tx] = h;
        dl[(size_t)(n0 + rr) * HH + k0 + tx] = __float2bfloat16(v - __bfloat162float(h));
    }
}

// ================= mma.sync GEMM =================
// CTA tile 128x128, 8 warps (4M x 2N), warp tile 32x64, BK=32, K_eff=3*1024.
// Epilogue by sel: 0/1 -> bf16 (Qh/Kh, *SCALE), 2 -> split bf16 (Vh/Vl), 3 -> fp32 out.
#define APAD 40          /* padded k-stride in bf16 (80B = 20 banks, conflict-free) */
#define NCHUNK 96

__global__ void __launch_bounds__(256)
k_gemm(int sel, const float* __restrict__ bias, float* __restrict__ Yext, float postscale)
{
    __shared__ __align__(16) __nv_bfloat16 sA[2][128 * APAD];
    __shared__ __align__(16) __nv_bfloat16 sB[2][128 * APAD];

    const int tid  = threadIdx.x;
    const int wid  = tid >> 5, lane = tid & 31;
    const int g    = lane >> 2, tig = lane & 3;
    const int wm   = (wid & 3) * 32;
    const int wn   = (wid >> 2) * 64;

    const int xsel = (sel == 3) ? 0 : sel;   // (unused for sel 3 except below)
    const __nv_bfloat16* Ah = (sel == 3) ? g_ch : g_xh + (size_t)xsel * ELEMS;
    const __nv_bfloat16* Al = (sel == 3) ? g_cl : g_xl + (size_t)xsel * ELEMS;
    const __nv_bfloat16* Bh = g_wt_h + (size_t)sel * HH * HH;
    const __nv_bfloat16* Bl = g_wt_l + (size_t)sel * HH * HH;

    const int nbase = blockIdx.x * 128;
    const int mbase = blockIdx.y * 128;

    const int u0 = tid, u1 = tid + 256;
    const int ar0 = u0 >> 2, aq0 = u0 & 3;
    const int ar1 = u1 >> 2, aq1 = u1 & 3;

    const uint32_t sA0 = smem_u32(&sA[0][0]);
    const uint32_t sB0 = smem_u32(&sB[0][0]);
    const uint32_t bufBytes = 128 * APAD * 2;

    #define LOAD_CHUNK(c, s) do {                                                   \
        const int _seg = (c) >> 5;                                                  \
        const int _kt  = ((c) & 31) << 5;                                           \
        const __nv_bfloat16* _a = (_seg == 2) ? Al : Ah;                            \
        const __nv_bfloat16* _b = (_seg == 1) ? Bl : Bh;                            \
        CP_ASYNC16(sA0 + (s) * bufBytes + (ar0 * APAD + aq0 * 8) * 2,               \
                   _a + (size_t)(mbase + ar0) * HH + _kt + aq0 * 8);                \
        CP_ASYNC16(sA0 + (s) * bufBytes + (ar1 * APAD + aq1 * 8) * 2,               \
                   _a + (size_t)(mbase + ar1) * HH + _kt + aq1 * 8);                \
        CP_ASYNC16(sB0 + (s) * bufBytes + (ar0 * APAD + aq0 * 8) * 2,               \
                   _b + (size_t)(nbase + ar0) * HH + _kt + aq0 * 8);                \
        CP_ASYNC16(sB0 + (s) * bufBytes + (ar1 * APAD + aq1 * 8) * 2,               \
                   _b + (size_t)(nbase + ar1) * HH + _kt + aq1 * 8);                \
        CP_COMMIT();                                                                \
    } while (0)

    float acc[2][8][4];
    #pragma unroll
    for (int mt = 0; mt < 2; mt++)
        #pragma unroll
        for (int nt = 0; nt < 8; nt++)
            #pragma unroll
            for (int q = 0; q < 4; q++) acc[mt][nt][q] = 0.0f;

    LOAD_CHUNK(0, 0);

    const int lrow = lane & 15;
    const int lcol = ((lane >> 4) & 1) * 16;

    for (int c = 0; c < NCHUNK; c++) {
        const int s = c & 1;
        CP_WAIT0();
        __syncthreads();
        if (c + 1 < NCHUNK) LOAD_CHUNK(c + 1, s ^ 1);

        const uint32_t aBase = sA0 + s * bufBytes;
        const uint32_t bBase = sB0 + s * bufBytes;
        #pragma unroll
        for (int ks = 0; ks < 2; ks++) {
            uint32_t af[2][4];
            #pragma unroll
            for (int mt = 0; mt < 2; mt++)
                LDSM_X4(af[mt][0], af[mt][1], af[mt][2], af[mt][3],
                        aBase + (wm + mt * 16 + lrow) * 80 + ks * 32 + lcol);
            #pragma unroll
            for (int nbp = 0; nbp < 4; nbp++) {
                uint32_t r0, r1, r2, r3;
                LDSM_X4(r0, r1, r2, r3,
                        bBase + (wn + nbp * 16 + lrow) * 80 + ks * 32 + lcol);
                uint32_t blo[2] = {r0, r2}, bhi[2] = {r1, r3};
                mma_bf16(acc[0][nbp * 2],     af[0], blo);
                mma_bf16(acc[0][nbp * 2 + 1], af[0], bhi);
                mma_bf16(acc[1][nbp * 2],     af[1], blo);
                mma_bf16(acc[1][nbp * 2 + 1], af[1], bhi);
            }
        }
        __syncthreads();
    }

    // epilogue
    #pragma unroll
    for (int mt = 0; mt < 2; mt++) {
        const int r0 = mbase + wm + mt * 16 + g;
        #pragma unroll
        for (int nt = 0; nt < 8; nt++) {
            const int n = nbase + wn + nt * 8 + tig * 2;
            const float2 bb = *(const float2*)(bias + n);
            float v00 = (acc[mt][nt][0] + bb.x) * postscale;
            float v01 = (acc[mt][nt][1] + bb.y) * postscale;
            float v10 = (acc[mt][nt][2] + bb.x) * postscale;
            float v11 = (acc[mt][nt][3] + bb.y) * postscale;
            if (sel == 3) {
                *(float2*)(Yext + (size_t)r0 * HH + n)       = make_float2(v00, v01);
                *(float2*)(Yext + (size_t)(r0 + 8) * HH + n) = make_float2(v10, v11);
            } else if (sel < 2) {
                __nv_bfloat16* Y16 = (sel == 0) ? g_Qh : g_Kh;
                *(__nv_bfloat162*)(Y16 + (size_t)r0 * HH + n) =
                    __halves2bfloat162(__float2bfloat16(v00), __float2bfloat16(v01));
                *(__nv_bfloat162*)(Y16 + (size_t)(r0 + 8) * HH + n) =
                    __halves2bfloat162(__float2bfloat16(v10), __float2bfloat16(v11));
            } else {
                __nv_bfloat16 h00 = __float2bfloat16(v00), h01 = __float2bfloat16(v01);
                __nv_bfloat16 h10 = __float2bfloat16(v10), h11 = __float2bfloat16(v11);
                *(__nv_bfloat162*)(g_Vh + (size_t)r0 * HH + n)       = __halves2bfloat162(h00, h01);
                *(__nv_bfloat162*)(g_Vh + (size_t)(r0 + 8) * HH + n) = __halves2bfloat162(h10, h11);
                *(__nv_bfloat162*)(g_Vl + (size_t)r0 * HH + n) = __halves2bfloat162(
                    __float2bfloat16(v00 - __bfloat162float(h00)),
                    __float2bfloat16(v01 - __bfloat162float(h01)));
                *(__nv_bfloat162*)(g_Vl + (size_t)(r0 + 8) * HH + n) = __halves2bfloat162(
                    __float2bfloat16(v10 - __bfloat162float(h10)),
                    __float2bfloat16(v11 - __bfloat162float(h11)));
            }
        }
    }
}

// ================= tensor-core causal flash attention =================
// Head slab (bh = n*16+h) is contiguous 2048x64. CTA: 64 q-rows, 128 thr (4 warps,
// each 16 rows). S via mma bf16; softmax in registers; PV 3-pass split bf16.
#define SP 72   /* smem row stride in bf16 (144B = 36 banks: ldmatrix conflict-free) */

__global__ void __launch_bounds__(128)
k_attn(const int* __restrict__ key_mask)
{
    __shared__ __align__(16) __nv_bfloat16 sQ[64 * SP];
    __shared__ __align__(16) __nv_bfloat16 sK[64 * SP];
    __shared__ __align__(16) __nv_bfloat16 sVh[64 * SP];
    __shared__ __align__(16) __nv_bfloat16 sVl[64 * SP];
    __shared__ int kms[64];

    const int tid = threadIdx.x;
    const int warp = tid >> 5, lane = tid & 31;
    const int g = lane >> 2, t = lane & 3;
    const int bh = blockIdx.y, n = bh >> 4;
    const size_t base = (size_t)bh * 128 * HH;
    const __nv_bfloat16* Qg  = g_Qh + base;
    const __nv_bfloat16* Kg  = g_Kh + base;
    const __nv_bfloat16* Vhg = g_Vh + base;
    const __nv_bfloat16* Vlg = g_Vl + base;

    const int qt = (int)gridDim.x - 1 - (int)blockIdx.x;  // heavy tiles first
    const int qbase = qt * 64;

    const uint32_t aQ  = smem_u32(sQ);
    const uint32_t aK  = smem_u32(sK);
    const uint32_t aVh = smem_u32(sVh);
    const uint32_t aVl = smem_u32(sVl);

    // Q tile: 64 rows x 64 bf16 = 512 x 16B segments
    #pragma unroll
    for (int u = tid; u < 512; u += 128) {
        const int row = u >> 3, seg = u & 7;
        CP_ASYNC16(aQ + row * (SP * 2) + seg * 16, Qg + (size_t)(qbase + row) * CD + seg * 8);
    }

    float m0 = -INFINITY, m1 = -INFINITY, l0 = 0.f, l1 = 0.f;
    float O[8][4];
    #pragma unroll
    for (int nb = 0; nb < 8; nb++)
        #pragma unroll
        for (int q = 0; q < 4; q++) O[nb][q] = 0.f;

    uint32_t aq[4][4];
    bool qloaded = false;

    const int lrow = lane & 15;
    const int lcol = ((lane >> 4) & 1) * 16;
    const int rowA = warp * 16 + g;   // in-tile q row (also rowA+8)

    for (int jt = 0; jt <= qt; jt++) {
        __syncthreads();   // smem reuse barrier
        #pragma unroll
        for (int u = tid; u < 512; u += 128) {
            const int row = u >> 3, seg = u & 7;
            const size_t gro = (size_t)(jt * 64 + row) * CD + seg * 8;
            CP_ASYNC16(aK  + row * (SP * 2) + seg * 16, Kg  + gro);
            CP_ASYNC16(aVh + row * (SP * 2) + seg * 16, Vhg + gro);
            CP_ASYNC16(aVl + row * (SP * 2) + seg * 16, Vlg + gro);
        }
        if (tid < 64) kms[tid] = key_mask[n * LQ + jt * 64 + tid];
        CP_COMMIT();
        CP_WAIT0();
        __syncthreads();

        if (!qloaded) {
            qloaded = true;
            #pragma unroll
            for (int ks = 0; ks < 4; ks++)
                LDSM_X4(aq[ks][0], aq[ks][1], aq[ks][2], aq[ks][3],
                        aQ + (warp * 16 + lrow) * (SP * 2) + ks * 32 + lcol);
        }

        // ---- S = Q K^T ----
        float sf[8][4];
        #pragma unroll
        for (int nb = 0; nb < 8; nb++)
            #pragma unroll
            for (int q = 0; q < 4; q++) sf[nb][q] = 0.f;

        #pragma unroll
        for (int ks = 0; ks < 4; ks++) {
            #pragma unroll
            for (int nbp = 0; nbp < 4; nbp++) {
                uint32_t r0, r1, r2, r3;
                LDSM_X4(r0, r1, r2, r3,
                        aK + (nbp * 16 + lrow) * (SP * 2) + ks * 32 + lcol);
                uint32_t blo[2] = {r0, r2}, bhi[2] = {r1, r3};
                mma_bf16(sf[nbp * 2],     aq[ks], blo);
                mma_bf16(sf[nbp * 2 + 1], aq[ks], bhi);
            }
        }

        // ---- mask ----
        const bool diag = (jt == qt);
        #pragma unroll
        for (int nb = 0; nb < 8; nb++) {
            const int c0 = nb * 8 + t * 2;
            const bool k0 = (kms[c0] != 0), k1 = (kms[c0 + 1] != 0);
            if (!k0 || (diag && c0 > rowA))         sf[nb][0] = -INFINITY;
            if (!k1 || (diag && c0 + 1 > rowA))     sf[nb][1] = -INFINITY;
            if (!k0 || (diag && c0 > rowA + 8))     sf[nb][2] = -INFINITY;
            if (!k1 || (diag && c0 + 1 > rowA + 8)) sf[nb][3] = -INFINITY;
        }

        // ---- online softmax (rows g and g+8; stats across quad via shfl) ----
        float mx0 = -INFINITY, mx1 = -INFINITY;
        #pragma unroll
        for (int nb = 0; nb < 8; nb++) {
            mx0 = fmaxf(mx0, fmaxf(sf[nb][0], sf[nb][1]));
            mx1 = fmaxf(mx1, fmaxf(sf[nb][2], sf[nb][3]));
        }
        mx0 = fmaxf(mx0, __shfl_xor_sync(0xffffffffu, mx0, 1));
        mx0 = fmaxf(mx0, __shfl_xor_sync(0xffffffffu, mx0, 2));
        mx1 = fmaxf(mx1, __shfl_xor_sync(0xffffffffu, mx1, 1));
        mx1 = fmaxf(mx1, __shfl_xor_sync(0xffffffffu, mx1, 2));
        const float mn0 = fmaxf(m0, mx0);
        const float mn1 = fmaxf(m1, mx1);
        const bool dead0 = (mn0 == -INFINITY), dead1 = (mn1 == -INFINITY);
        const float alpha0 = dead0 ? 1.f : __expf(m0 - mn0);
        const float alpha1 = dead1 ? 1.f : __expf(m1 - mn1);
        m0 = mn0; m1 = mn1;

        float rs0 = 0.f, rs1 = 0.f;
        #pragma unroll
        for (int nb = 0; nb < 8; nb++) {
            sf[nb][0] = dead0 ? 0.f : __expf(sf[nb][0] - mn0);
            sf[nb][1] = dead0 ? 0.f : __expf(sf[nb][1] - mn0);
            sf[nb][2] = dead1 ? 0.f : __expf(sf[nb][2] - mn1);
            sf[nb][3] = dead1 ? 0.f : __expf(sf[nb][3] - mn1);
            rs0 += sf[nb][0] + sf[nb][1];
            rs1 += sf[nb][2] + sf[nb][3];
        }
        rs0 += __shfl_xor_sync(0xffffffffu, rs0, 1);
        rs0 += __shfl_xor_sync(0xffffffffu, rs0, 2);
        rs1 += __shfl_xor_sync(0xffffffffu, rs1, 1);
        rs1 += __shfl_xor_sync(0xffffffffu, rs1, 2);
        l0 = l0 * alpha0 + rs0;
        l1 = l1 * alpha1 + rs1;

        #pragma unroll
        for (int nb = 0; nb < 8; nb++) {
            O[nb][0] *= alpha0; O[nb][1] *= alpha0;
            O[nb][2] *= alpha1; O[nb][3] *= alpha1;
        }

        // ---- P -> split bf16 A-frags (register recast, no smem) ----
        uint32_t pha[4][4], pla[4][4];
        #pragma unroll
        for (int ks = 0; ks < 4; ks++) {
            #pragma unroll
            for (int q = 0; q < 4; q++) {
                const int nb = 2 * ks + (q >> 1);
                const int e  = (q & 1) * 2;
                const float x0 = sf[nb][e], x1 = sf[nb][e + 1];
                const __nv_bfloat16 h0 = __float2bfloat16(x0);
                const __nv_bfloat16 h1 = __float2bfloat16(x1);
                __nv_bfloat162 hh = __halves2bfloat162(h0, h1);
                __nv_bfloat162 ll = __halves2bfloat162(
                    __float2bfloat16(x0 - __bfloat162float(h0)),
                    __float2bfloat16(x1 - __bfloat162float(h1)));
                pha[ks][q] = *(uint32_t*)&hh;
                pla[ks][q] = *(uint32_t*)&ll;
            }
        }

        // ---- O += Ph*Vh + Pl*Vh + Ph*Vl ----
        #pragma unroll
        for (int ks = 0; ks < 4; ks++) {
            #pragma unroll
            for (int vb = 0; vb < 4; vb++) {
                uint32_t h0, h1, h2, h3, q0, q1, q2, q3;
                LDSM_X4_T(h0, h1, h2, h3,
                          aVh + (ks * 16 + lrow) * (SP * 2) + vb * 32 + lcol);
                LDSM_X4_T(q0, q1, q2, q3,
                          aVl + (ks * 16 + lrow) * (SP * 2) + vb * 32 + lcol);
                uint32_t bh0[2] = {h0, h1}, bh1[2] = {h2, h3};
                uint32_t bl0[2] = {q0, q1}, bl1[2] = {q2, q3};
                mma_bf16(O[vb * 2],     pha[ks], bh0);
                mma_bf16(O[vb * 2 + 1], pha[ks], bh1);
                mma_bf16(O[vb * 2],     pla[ks], bh0);
                mma_bf16(O[vb * 2 + 1], pla[ks], bh1);
                mma_bf16(O[vb * 2],     pha[ks], bl0);
                mma_bf16(O[vb * 2 + 1], pha[ks], bl1);
            }
        }
    }

    // ---- epilogue: normalize + write ctx as split bf16 ----
    const float inv0 = 1.f / l0, inv1 = 1.f / l1;
    const int grow0 = qbase + warp * 16 + g;
    #pragma unroll
    for (int nb = 0; nb < 8; nb++) {
        const int c = nb * 8 + t * 2;
        const float v00 = O[nb][0] * inv0, v01 = O[nb][1] * inv0;
        const float v10 = O[nb][2] * inv1, v11 = O[nb][3] * inv1;
        const __nv_bfloat16 h00 = __float2bfloat16(v00), h01 = __float2bfloat16(v01);
        const __nv_bfloat16 h10 = __float2bfloat16(v10), h11 = __float2bfloat16(v11);
        *(__nv_bfloat162*)(g_ch + base + (size_t)grow0 * CD + c) = __halves2bfloat162(h00, h01);
        *(__nv_bfloat162*)(g_ch + base + (size_t)(grow0 + 8) * CD + c) = __halves2bfloat162(h10, h11);
        *(__nv_bfloat162*)(g_cl + base + (size_t)grow0 * CD + c) = __halves2bfloat162(
            __float2bfloat16(v00 - __bfloat162float(h00)),
            __float2bfloat16(v01 - __bfloat162float(h01)));
        *(__nv_bfloat162*)(g_cl + base + (size_t)(grow0 + 8) * CD + c) = __halves2bfloat162(
            __float2bfloat16(v10 - __bfloat162float(h10)),
            __float2bfloat16(v11 - __bfloat162float(h11)));
    }
}

// ================= launch =================
extern "C" void kernel_launch(void* const* d_in, const int* in_sizes, int n_in,
                              void* d_out, int out_size)
{
    const float* Q  = (const float*)d_in[0];
    const float* K  = (const float*)d_in[1];
    const float* V  = (const float*)d_in[2];
    const int*   km = (const int*)  d_in[3];
    const float* Wq = (const float*)d_in[4];
    const float* bq = (const float*)d_in[5];
    const float* Wk = (const float*)d_in[6];
    const float* bk = (const float*)d_in[7];
    const float* Wv = (const float*)d_in[8];
    const float* bv = (const float*)d_in[9];
    const float* Wo = (const float*)d_in[10];
    const float* bo = (const float*)d_in[11];
    float* out = (float*)d_out;

    // prep
    k_prep_w<<<dim3(32, 32, 4), dim3(32, 8)>>>(Wq, Wk, Wv, Wo);
    k_prep_x<<<(unsigned)(ELEMS / (4 * 256)), 256>>>(Q, 0);
    k_prep_x<<<(unsigned)(ELEMS / (4 * 256)), 256>>>(K, 1);
    k_prep_x<<<(unsigned)(ELEMS / (4 * 256)), 256>>>(V, 2);

    // QKV projections (bf16 / split-bf16 outputs for attention)
    dim3 gg(HH / 128, (NB * LQ) / 128);
    k_gemm<<<gg, 256>>>(0, bq, nullptr, SCALE);
    k_gemm<<<gg, 256>>>(1, bk, nullptr, SCALE);
    k_gemm<<<gg, 256>>>(2, bv, nullptr, 1.0f);

    // attention (tensor cores)
    k_attn<<<dim3(LQ / 64, NB * NHEAD), 128>>>(km);

    // out projection (reads split ctx written by attention)
    k_gemm<<<gg, 256>>>(3, bo, out, 1.0f);
}